// round 2
// baseline (speedup 1.0000x reference)
#include <cuda_runtime.h>
#include <cuda_bf16.h>
#include <cstdint>

// LoRA low-rank fused kernel:
//   t[m][r]  = sum_i x[m][i] * A[r][i]                (rank-16 projection)
//   out[m][o]= 2 * sum_r t[m][r] * B[o][r] + bias[o]
//
// One fused kernel. Block handles MTILE=32 rows of m (8192 total rows).
// Packed f32x2 FMAs (fma.rn.f32x2) double fp32 throughput on sm_103a.

#define IN_F   4096
#define OUT_F  4096
#define RANK   16
#define M_TOT  8192
#define CK     512          // A chunk (i-dimension) staged in smem
#define MTILE  32           // m rows per block
#define RPW    8            // m rows per warp (4 warps/block)

__device__ __forceinline__ unsigned long long pk2(float lo, float hi) {
    unsigned long long r;
    asm("mov.b64 %0, {%1,%2};" : "=l"(r) : "f"(lo), "f"(hi));
    return r;
}
__device__ __forceinline__ void fma2(unsigned long long &d,
                                     unsigned long long a,
                                     unsigned long long b) {
    asm("fma.rn.f32x2 %0, %1, %2, %0;" : "+l"(d) : "l"(a), "l"(b));
}
__device__ __forceinline__ float2 up2(unsigned long long v) {
    float2 f;
    asm("mov.b64 {%0,%1}, %2;" : "=f"(f.x), "=f"(f.y) : "l"(v));
    return f;
}

__global__ __launch_bounds__(128)
void lora_fused_kernel(const float* __restrict__ x,
                       const float* __restrict__ A,      // [16, 4096]
                       const float* __restrict__ B,      // [4096, 16]
                       const float* __restrict__ bias,   // [4096]
                       float* __restrict__ out)
{
    __shared__ float As[RANK][CK];       // staged A chunk (SoA planes, conflict-free LDS.128)
    __shared__ float t_s[MTILE][RANK];   // per-block t, scaled by 2

    const int tid  = threadIdx.x;
    const int lane = tid & 31;
    const int w    = tid >> 5;           // warp id 0..3
    const int mbase = blockIdx.x * MTILE;

    // ---------------- Phase 1: t = x @ A^T ----------------
    // Each warp owns 8 consecutive m rows; lanes split i.
    // Accumulators packed over m-pairs: acc[mp][r] = (t[2mp], t[2mp+1]) partials.
    unsigned long long acc[4][RANK];
    #pragma unroll
    for (int mp = 0; mp < 4; ++mp)
        #pragma unroll
        for (int r = 0; r < RANK; ++r)
            acc[mp][r] = 0ull;

    const float* xw = x + (size_t)(mbase + w * RPW) * IN_F;

    for (int i0 = 0; i0 < IN_F; i0 += CK) {
        __syncthreads();
        // stage A chunk: As[r][il] = A[r][i0+il], vectorized float4
        for (int k = tid; k < RANK * (CK / 4); k += 128) {
            const int r  = k >> 7;            // CK/4 == 128
            const int il = (k & 127) << 2;
            *(float4*)&As[r][il] = *(const float4*)&A[r * IN_F + i0 + il];
        }
        __syncthreads();

        #pragma unroll
        for (int s = 0; s < CK / 128; ++s) {
            const int il = s * 128 + lane * 4;

            // load 8 rows of x (float4 each), pack into m-pair f32x2 operands
            unsigned long long xp[4][4];
            #pragma unroll
            for (int mp = 0; mp < 4; ++mp) {
                const float4 xa = *(const float4*)(xw + (size_t)(2 * mp)     * IN_F + i0 + il);
                const float4 xb = *(const float4*)(xw + (size_t)(2 * mp + 1) * IN_F + i0 + il);
                xp[mp][0] = pk2(xa.x, xb.x);
                xp[mp][1] = pk2(xa.y, xb.y);
                xp[mp][2] = pk2(xa.z, xb.z);
                xp[mp][3] = pk2(xa.w, xb.w);
            }

            #pragma unroll
            for (int r = 0; r < RANK; ++r) {
                const float4 a4 = *(const float4*)&As[r][il];
                const float av[4] = {a4.x, a4.y, a4.z, a4.w};
                #pragma unroll
                for (int j = 0; j < 4; ++j) {
                    const unsigned long long aa = pk2(av[j], av[j]);
                    #pragma unroll
                    for (int mp = 0; mp < 4; ++mp)
                        fma2(acc[mp][r], xp[mp][j], aa);
                }
            }
        }
    }

    // warp-reduce each packed accumulator across 32 lanes; lane 0 writes t (x2 scaling folded in)
    #pragma unroll
    for (int mp = 0; mp < 4; ++mp) {
        #pragma unroll
        for (int r = 0; r < RANK; ++r) {
            float2 f = up2(acc[mp][r]);
            #pragma unroll
            for (int off = 16; off; off >>= 1) {
                f.x += __shfl_down_sync(0xffffffffu, f.x, off);
                f.y += __shfl_down_sync(0xffffffffu, f.y, off);
            }
            if (lane == 0) {
                t_s[w * RPW + 2 * mp][r]     = 2.0f * f.x;
                t_s[w * RPW + 2 * mp + 1][r] = 2.0f * f.y;
            }
        }
    }
    __syncthreads();

    // ---------------- Phase 2: out = t @ B^T + bias ----------------
    // Warp w handles the same 8 m rows; lanes split output columns o.
    unsigned long long tp[4][RANK];
    #pragma unroll
    for (int mp = 0; mp < 4; ++mp)
        #pragma unroll
        for (int r = 0; r < RANK; ++r)
            tp[mp][r] = pk2(t_s[w * RPW + 2 * mp][r], t_s[w * RPW + 2 * mp + 1][r]);

    float* outw = out + (size_t)(mbase + w * RPW) * OUT_F;

    for (int ob = 0; ob < OUT_F; ob += 32) {
        const int o = ob + lane;
        const float4* Bp = (const float4*)(B + o * RANK);
        const float4 b0 = Bp[0], b1 = Bp[1], b2 = Bp[2], b3 = Bp[3];
        const float bv[16] = {b0.x, b0.y, b0.z, b0.w,
                              b1.x, b1.y, b1.z, b1.w,
                              b2.x, b2.y, b2.z, b2.w,
                              b3.x, b3.y, b3.z, b3.w};
        const float bi = __ldg(bias + o);

        unsigned long long a2[4];
        #pragma unroll
        for (int mp = 0; mp < 4; ++mp) a2[mp] = pk2(bi, bi);

        #pragma unroll
        for (int r = 0; r < RANK; ++r) {
            const unsigned long long bb = pk2(bv[r], bv[r]);
            #pragma unroll
            for (int mp = 0; mp < 4; ++mp)
                fma2(a2[mp], tp[mp][r], bb);
        }

        #pragma unroll
        for (int mp = 0; mp < 4; ++mp) {
            const float2 v = up2(a2[mp]);
            outw[(size_t)(2 * mp)     * OUT_F + o] = v.x;
            outw[(size_t)(2 * mp + 1) * OUT_F + o] = v.y;
        }
    }
}

extern "C" void kernel_launch(void* const* d_in, const int* in_sizes, int n_in,
                              void* d_out, int out_size) {
    const float* x    = (const float*)d_in[0];   // [4,2048,4096] -> [8192,4096]
    const float* A    = (const float*)d_in[1];   // [16,4096]
    const float* B    = (const float*)d_in[2];   // [4096,16]
    const float* bias = (const float*)d_in[3];   // [4096]
    float* out = (float*)d_out;                  // [8192,4096]

    lora_fused_kernel<<<M_TOT / MTILE, 128>>>(x, A, B, bias, out);
}